// round 1
// baseline (speedup 1.0000x reference)
#include <cuda_runtime.h>

#define B_   2
#define NT_  1024
#define ND_  512
#define NH_  196
#define HP_  256      // padded hidden dim (zeros for h >= 196)
#define KL_  128
#define ROWS_ 16

// scratch (device globals: allocation-free)
__device__ float g_wj[B_ * 8 * HP_];    // per-j weights: [w_xn, M1x(3), w_vn, M1v(3)]
__device__ float g_wc[B_ * 10 * HP_];   // per-i weights: [w_N, w_x0n, M0x(3), w_vbn, M0v(3), b0]
__device__ float g_hm[B_ * NT_ * NH_];  // pooled hidden (after leaky+mean), pre-W1

typedef unsigned long long u64t;

__device__ __forceinline__ u64t pack2(float x, float y) {
    u64t r; asm("mov.b64 %0, {%1, %2};" : "=l"(r) : "f"(x), "f"(y)); return r;
}
__device__ __forceinline__ float2 unpack2(u64t v) {
    float2 r; asm("mov.b64 {%0, %1}, %2;" : "=f"(r.x), "=f"(r.y) : "l"(v)); return r;
}
__device__ __forceinline__ u64t ffma2(u64t a, u64t b, u64t c) {
    u64t d; asm("fma.rn.f32x2 %0, %1, %2, %3;" : "=l"(d) : "l"(a), "l"(b), "l"(c)); return d;
}

// ---------------------------------------------------------------------------
// Kernel 1: fold basis into W0 rows (tiny)
// s layout: 0:N 1:|x0| 2-7:x0b 8:|vb| 9-14:vbb 15:|x| 16-21:xb 22:|v| 23-28:vb
// ---------------------------------------------------------------------------
__global__ void precomp_kernel(const float* __restrict__ W0,
                               const float* __restrict__ b0,
                               const float* __restrict__ basis) {
    int b = blockIdx.x, h = threadIdx.x;
    float* wj = g_wj + b * 8 * HP_;
    float* wc = g_wc + b * 10 * HP_;
    if (h >= NH_) {
        for (int r = 0; r < 8;  r++) wj[r * HP_ + h] = 0.f;
        for (int r = 0; r < 10; r++) wc[r * HP_ + h] = 0.f;
        return;
    }
    const float* bs = basis + b * 6 * 3;
    wj[0 * HP_ + h] = W0[15 * NH_ + h];   // |x|
    wj[4 * HP_ + h] = W0[22 * NH_ + h];   // |vc|
    wc[0 * HP_ + h] = W0[0 * NH_ + h];    // N
    wc[1 * HP_ + h] = W0[1 * NH_ + h];    // |x0|
    wc[5 * HP_ + h] = W0[8 * NH_ + h];    // |vbulk|
    wc[9 * HP_ + h] = b0[h];
    for (int d = 0; d < 3; d++) {
        float m0x = 0.f, m0v = 0.f, m1 = 0.f, m2 = 0.f;
        for (int k = 0; k < 6; k++) {
            float bb = bs[k * 3 + d];
            m0x += bb * W0[(2  + k) * NH_ + h];
            m0v += bb * W0[(9  + k) * NH_ + h];
            m1  += bb * W0[(16 + k) * NH_ + h];
            m2  += bb * W0[(23 + k) * NH_ + h];
        }
        wj[(1 + d) * HP_ + h] = m1;
        wj[(5 + d) * HP_ + h] = m2;
        wc[(2 + d) * HP_ + h] = m0x;
        wc[(6 + d) * HP_ + h] = m0v;
    }
}

// ---------------------------------------------------------------------------
// Kernel 2: one CTA per (b,i). vbulk reduce -> stage 8 per-j features ->
// f32x2 j-packed dot with |.| accumulation -> analytic mean(pre) ->
// pooled hidden to g_hm.
// ---------------------------------------------------------------------------
__global__ __launch_bounds__(128) void main_kernel(
    const float* __restrict__ x0g, const float* __restrict__ xg,
    const float* __restrict__ Ng,  const float* __restrict__ vg) {
    __shared__ float4 ftr4[8 * 128];           // features transposed: ftr[f][512]
    float* ftr = (float*)ftr4;
    __shared__ float red[32];

    int t = threadIdx.x;
    int blk = blockIdx.x;
    int b = blk >> 10, i = blk & (NT_ - 1);
    int lane = t & 31, w = t >> 5;
    int base = (b * NT_ + i) * ND_ * 3;

    // --- phase 1: vbulk (keep v in regs for phase 2) ---
    float vxr[4], vyr[4], vzr[4];
    float s0 = 0.f, s1 = 0.f, s2 = 0.f;
#pragma unroll
    for (int r = 0; r < 4; r++) {
        int j = t + r * 128;
        const float* vp = vg + base + j * 3;
        float a = vp[0], bb = vp[1], c = vp[2];
        vxr[r] = a; vyr[r] = bb; vzr[r] = c;
        s0 += a; s1 += bb; s2 += c;
    }
#pragma unroll
    for (int off = 16; off; off >>= 1) {
        s0 += __shfl_xor_sync(0xffffffffu, s0, off);
        s1 += __shfl_xor_sync(0xffffffffu, s1, off);
        s2 += __shfl_xor_sync(0xffffffffu, s2, off);
    }
    if (lane == 0) { red[w * 8 + 0] = s0; red[w * 8 + 1] = s1; red[w * 8 + 2] = s2; }
    __syncthreads();
    float vb0 = (red[0] + red[8]  + red[16] + red[24]) * (1.f / ND_);
    float vb1 = (red[1] + red[9]  + red[17] + red[25]) * (1.f / ND_);
    float vb2 = (red[2] + red[10] + red[18] + red[26]) * (1.f / ND_);
    __syncthreads();

    // --- phase 2: stage per-j features + per-feature sums ---
    float fs[8] = {0.f, 0.f, 0.f, 0.f, 0.f, 0.f, 0.f, 0.f};
#pragma unroll
    for (int r = 0; r < 4; r++) {
        int j = t + r * 128;
        const float* xp = xg + base + j * 3;
        float a = xp[0], bb = xp[1], c = xp[2];
        float d  = a * a + bb * bb + c * c;
        float ri = rsqrtf(d);
        float n  = d * ri;
        float e1 = a * ri, e2 = bb * ri, e3 = c * ri;
        ftr[0 * 512 + j] = n;  ftr[1 * 512 + j] = e1;
        ftr[2 * 512 + j] = e2; ftr[3 * 512 + j] = e3;
        fs[0] += n; fs[1] += e1; fs[2] += e2; fs[3] += e3;
        float c0 = vxr[r] - vb0, c1 = vyr[r] - vb1, c2 = vzr[r] - vb2;
        d  = c0 * c0 + c1 * c1 + c2 * c2;
        ri = rsqrtf(d);
        n  = d * ri;
        e1 = c0 * ri; e2 = c1 * ri; e3 = c2 * ri;
        ftr[4 * 512 + j] = n;  ftr[5 * 512 + j] = e1;
        ftr[6 * 512 + j] = e2; ftr[7 * 512 + j] = e3;
        fs[4] += n; fs[5] += e1; fs[6] += e2; fs[7] += e3;
    }
#pragma unroll
    for (int off = 16; off; off >>= 1)
#pragma unroll
        for (int f = 0; f < 8; f++) fs[f] += __shfl_xor_sync(0xffffffffu, fs[f], off);
    if (lane == 0) {
#pragma unroll
        for (int f = 0; f < 8; f++) red[w * 8 + f] = fs[f];
    }
    __syncthreads();
    float fm[8];
#pragma unroll
    for (int f = 0; f < 8; f++)
        fm[f] = (red[f] + red[8 + f] + red[16 + f] + red[24 + f]) * (1.f / ND_);

    // --- per-i constant C (cheap, redundant per thread) ---
    float Nv = Ng[b * NT_ + i];
    const float* x0p = x0g + (b * NT_ + i) * 3;
    float p0 = x0p[0], p1 = x0p[1], p2 = x0p[2];
    float d0 = p0 * p0 + p1 * p1 + p2 * p2;
    float ri0 = rsqrtf(d0);
    float x0n = d0 * ri0;
    float u0 = p0 * ri0, u1 = p1 * ri0, u2 = p2 * ri0;
    float dv = vb0 * vb0 + vb1 * vb1 + vb2 * vb2;
    float riv = rsqrtf(dv);
    float vbn = dv * riv;
    float q0 = vb0 * riv, q1 = vb1 * riv, q2 = vb2 * riv;

    const float* wj = g_wj + b * 8 * HP_;
    const float* wc = g_wc + b * 10 * HP_;
    int h0 = t, h1i = t + 128;

    float C0, C1;
    {
        float c;
        c  = wc[9 * HP_ + h0];
        c += Nv  * wc[0 * HP_ + h0];
        c += x0n * wc[1 * HP_ + h0];
        c += u0 * wc[2 * HP_ + h0] + u1 * wc[3 * HP_ + h0] + u2 * wc[4 * HP_ + h0];
        c += vbn * wc[5 * HP_ + h0];
        c += q0 * wc[6 * HP_ + h0] + q1 * wc[7 * HP_ + h0] + q2 * wc[8 * HP_ + h0];
        C0 = c;
        c  = wc[9 * HP_ + h1i];
        c += Nv  * wc[0 * HP_ + h1i];
        c += x0n * wc[1 * HP_ + h1i];
        c += u0 * wc[2 * HP_ + h1i] + u1 * wc[3 * HP_ + h1i] + u2 * wc[4 * HP_ + h1i];
        c += vbn * wc[5 * HP_ + h1i];
        c += q0 * wc[6 * HP_ + h1i] + q1 * wc[7 * HP_ + h1i] + q2 * wc[8 * HP_ + h1i];
        C1 = c;
    }

    float w0s[8], w1s[8];
    u64t  w0p[8], w1p[8];
#pragma unroll
    for (int f = 0; f < 8; f++) {
        w0s[f] = wj[f * HP_ + h0];
        w1s[f] = wj[f * HP_ + h1i];
        w0p[f] = pack2(w0s[f], w0s[f]);
        w1p[f] = pack2(w1s[f], w1s[f]);
    }
    u64t C0p = pack2(C0, C0), C1p = pack2(C1, C1);

    // --- phase 3: hot loop. acc = sum_j |pre_j| for 2 h's, f32x2 over j ---
    float a0A = 0.f, a0B = 0.f, a1A = 0.f, a1B = 0.f;
#pragma unroll 1
    for (int j4 = 0; j4 < 512; j4 += 4) {
        ulonglong2 qq[8];
#pragma unroll
        for (int f = 0; f < 8; f++)
            qq[f] = *(const ulonglong2*)(ftr + f * 512 + j4);
        u64t p; float2 e;
        p = C0p;
#pragma unroll
        for (int f = 0; f < 8; f++) p = ffma2(qq[f].x, w0p[f], p);
        e = unpack2(p); a0A += fabsf(e.x); a0B += fabsf(e.y);
        p = C0p;
#pragma unroll
        for (int f = 0; f < 8; f++) p = ffma2(qq[f].y, w0p[f], p);
        e = unpack2(p); a0A += fabsf(e.x); a0B += fabsf(e.y);
        p = C1p;
#pragma unroll
        for (int f = 0; f < 8; f++) p = ffma2(qq[f].x, w1p[f], p);
        e = unpack2(p); a1A += fabsf(e.x); a1B += fabsf(e.y);
        p = C1p;
#pragma unroll
        for (int f = 0; f < 8; f++) p = ffma2(qq[f].y, w1p[f], p);
        e = unpack2(p); a1A += fabsf(e.x); a1B += fabsf(e.y);
    }

    // mean(leaky) = 0.505*mean(pre) + 0.495*mean|pre|; mean(pre) is analytic
    float S0 = C0, S1 = C1;
#pragma unroll
    for (int f = 0; f < 8; f++) { S0 += fm[f] * w0s[f]; S1 += fm[f] * w1s[f]; }
    float hm0 = 0.505f * S0 + (0.495f / ND_) * (a0A + a0B);
    float hm1 = 0.505f * S1 + (0.495f / ND_) * (a1A + a1B);
    float* hmp = g_hm + (b * NT_ + i) * NH_;
    hmp[h0] = hm0;
    if (h1i < NH_) hmp[h1i] = hm1;
}

// ---------------------------------------------------------------------------
// Kernel 3: row-blocked tail: h2 = leaky(hm@W1+b1); out = h2@W2+b2.
// 128 CTAs x 16 rows so W1/W2 L2 traffic stays tiny.
// ---------------------------------------------------------------------------
__global__ __launch_bounds__(256) void tail_kernel(
    const float* __restrict__ W1, const float* __restrict__ b1,
    const float* __restrict__ W2, const float* __restrict__ b2,
    float* __restrict__ out) {
    __shared__ float hm_s[ROWS_ * NH_];
    __shared__ float h2_s[ROWS_ * NH_];
    int t = threadIdx.x;
    int row0 = blockIdx.x * ROWS_;

    for (int idx = t; idx < ROWS_ * NH_; idx += 256)
        hm_s[idx] = g_hm[row0 * NH_ + idx];
    __syncthreads();

    for (int job = t; job < NH_ * 4; job += 256) {
        int rg = job / NH_;
        int h  = job - rg * NH_;
        const float* r0p = hm_s + (rg * 4 + 0) * NH_;
        const float* r1p = hm_s + (rg * 4 + 1) * NH_;
        const float* r2p = hm_s + (rg * 4 + 2) * NH_;
        const float* r3p = hm_s + (rg * 4 + 3) * NH_;
        float bv = b1[h];
        float a0 = bv, a1 = bv, a2 = bv, a3 = bv;
#pragma unroll 4
        for (int k = 0; k < NH_; k++) {
            float wv = W1[k * NH_ + h];
            a0 = fmaf(r0p[k], wv, a0);
            a1 = fmaf(r1p[k], wv, a1);
            a2 = fmaf(r2p[k], wv, a2);
            a3 = fmaf(r3p[k], wv, a3);
        }
        h2_s[(rg * 4 + 0) * NH_ + h] = fmaxf(a0, 0.01f * a0);
        h2_s[(rg * 4 + 1) * NH_ + h] = fmaxf(a1, 0.01f * a1);
        h2_s[(rg * 4 + 2) * NH_ + h] = fmaxf(a2, 0.01f * a2);
        h2_s[(rg * 4 + 3) * NH_ + h] = fmaxf(a3, 0.01f * a3);
    }
    __syncthreads();

    for (int job = t; job < KL_ * 4; job += 256) {
        int rg = job >> 7;
        int o  = job & (KL_ - 1);
        const float* r0p = h2_s + (rg * 4 + 0) * NH_;
        const float* r1p = h2_s + (rg * 4 + 1) * NH_;
        const float* r2p = h2_s + (rg * 4 + 2) * NH_;
        const float* r3p = h2_s + (rg * 4 + 3) * NH_;
        float bv = b2[o];
        float a0 = bv, a1 = bv, a2 = bv, a3 = bv;
#pragma unroll 4
        for (int k = 0; k < NH_; k++) {
            float wv = W2[k * KL_ + o];
            a0 = fmaf(r0p[k], wv, a0);
            a1 = fmaf(r1p[k], wv, a1);
            a2 = fmaf(r2p[k], wv, a2);
            a3 = fmaf(r3p[k], wv, a3);
        }
        out[(row0 + rg * 4 + 0) * KL_ + o] = a0;
        out[(row0 + rg * 4 + 1) * KL_ + o] = a1;
        out[(row0 + rg * 4 + 2) * KL_ + o] = a2;
        out[(row0 + rg * 4 + 3) * KL_ + o] = a3;
    }
}

// ---------------------------------------------------------------------------
extern "C" void kernel_launch(void* const* d_in, const int* in_sizes, int n_in,
                              void* d_out, int out_size) {
    const float* x0    = (const float*)d_in[0];
    const float* x     = (const float*)d_in[1];
    const float* N     = (const float*)d_in[2];
    const float* basis = (const float*)d_in[3];
    const float* v     = (const float*)d_in[4];
    const float* W0    = (const float*)d_in[5];
    const float* b0    = (const float*)d_in[6];
    const float* W1    = (const float*)d_in[7];
    const float* b1    = (const float*)d_in[8];
    const float* W2    = (const float*)d_in[9];
    const float* b2    = (const float*)d_in[10];

    precomp_kernel<<<B_, HP_>>>(W0, b0, basis);
    main_kernel<<<B_ * NT_, 128>>>(x0, x, N, v);
    tail_kernel<<<(B_ * NT_) / ROWS_, 256>>>(W1, b1, W2, b2, (float*)d_out);
}